// round 2
// baseline (speedup 1.0000x reference)
#include <cuda_runtime.h>

#define C_IN 256
#define O_OUT 256
#define CKTOT 2304   // C_IN * 9

// Transposed deform weights: wT[ck][o], ck = c*9+k. Static device scratch (no allocs).
__device__ float g_wT_T[CKTOT * O_OUT];
__device__ float g_wT_S[CKTOT * O_OUT];

// ---------------------------------------------------------------------------
// Weight transpose: w[o][c][3][3] -> wT[c*9+k][o]
// ---------------------------------------------------------------------------
__global__ void transpose_w_kernel(const float* __restrict__ w, int which) {
    float* wT = which ? g_wT_S : g_wT_T;
    int t = blockIdx.x * 256 + threadIdx.x;
    if (t < CKTOT * O_OUT) {
        int ck = t >> 8;          // / 256
        int o  = t & 255;
        wT[t] = w[o * CKTOT + ck];
    }
}

// ---------------------------------------------------------------------------
// Offset conv: 3x3, stride 1, pad 1, 256 -> 18 channels, + bias.
// One block = one 16x16 spatial tile of one batch. 256 threads = 1/pixel.
// ---------------------------------------------------------------------------
template <int H, int W>
__global__ void __launch_bounds__(256) offset_conv_kernel(
    const float* __restrict__ x, const float* __restrict__ wgt,
    const float* __restrict__ bias, float* __restrict__ out)
{
    const int HW = H * W;
    const int tiles = (H / 16) * (W / 16);
    const int b    = blockIdx.x / tiles;
    const int tile = blockIdx.x % tiles;
    const int h0 = (tile / (W / 16)) * 16;
    const int w0 = (tile % (W / 16)) * 16;

    __shared__ float sx[8 * 18 * 18];   // 8 channels, 18x18 halo tile
    __shared__ float sw[18 * 8 * 9];    // 18 out-ch, 8 in-ch, 9 taps

    const int tid = threadIdx.x;
    const int ty = tid >> 4, tx = tid & 15;

    float acc[18];
#pragma unroll
    for (int i = 0; i < 18; i++) acc[i] = 0.f;

    const float* xb = x + (size_t)b * C_IN * HW;

    for (int c0 = 0; c0 < C_IN; c0 += 8) {
        __syncthreads();
        // load halo x tile (zero padding)
        for (int e = tid; e < 8 * 324; e += 256) {
            int c = e / 324, r = e % 324;
            int yy = r / 18 - 1 + h0;
            int xx = r % 18 - 1 + w0;
            float v = 0.f;
            if (yy >= 0 && yy < H && xx >= 0 && xx < W)
                v = xb[(c0 + c) * HW + yy * W + xx];
            sx[e] = v;
        }
        // load weight chunk: sw[oc*72 + c*9 + tap]
        for (int e = tid; e < 18 * 72; e += 256) {
            int oc = e / 72, r = e % 72;
            sw[e] = wgt[oc * CKTOT + c0 * 9 + r];
        }
        __syncthreads();

#pragma unroll
        for (int c = 0; c < 8; c++) {
            float xv[9];
#pragma unroll
            for (int t = 0; t < 9; t++)
                xv[t] = sx[c * 324 + (ty + t / 3) * 18 + (tx + t % 3)];
#pragma unroll
            for (int oc = 0; oc < 18; oc++) {
#pragma unroll
                for (int t = 0; t < 9; t++)
                    acc[oc] += xv[t] * sw[oc * 72 + c * 9 + t];
            }
        }
    }

    const int h = h0 + ty, w = w0 + tx;
    float* ob = out + (size_t)b * 18 * HW + h * W + w;
#pragma unroll
    for (int oc = 0; oc < 18; oc++)
        ob[oc * HW] = acc[oc] + bias[oc];
}

// ---------------------------------------------------------------------------
// Deformable conv v1 (3x3, pad 1, 1 group, no bias).
// One block = 16 contiguous (row-major) spatial positions of one batch.
// Phase 0: bilinear corner idx/weights per (tap, pos) -> smem.
// Phase 1: gather samp[ck_local][p] for a 64-channel chunk (576 x 16 tile).
// Phase 2: thread = output channel; GEMM accumulate over 576 ck per chunk.
// ---------------------------------------------------------------------------
template <int H, int W>
__global__ void __launch_bounds__(256) deform_conv_kernel(
    const float* __restrict__ x, const float* __restrict__ off,
    int which, float* __restrict__ out)
{
    const int HW = H * W;
    const int nT = HW / 16;
    const int b = blockIdx.x / nT;
    const int tileBase = (blockIdx.x % nT) * 16;
    const float* wT = which ? g_wT_S : g_wT_T;

    __shared__ float samp[576 * 16];    // 36,864 B
    __shared__ int   cIdx[144 * 4];
    __shared__ float cW[144 * 4];

    const int tid = threadIdx.x;

    // ---- Phase 0: bilinear corners for 9 taps x 16 positions ----
    if (tid < 144) {
        int k = tid >> 4, p = tid & 15;
        int pos = tileBase + p;
        int h = pos / W, w = pos % W;
        const float* ob = off + (size_t)b * 18 * HW + pos;
        float dy = ob[(2 * k) * HW];
        float dx = ob[(2 * k + 1) * HW];
        float sy = (float)(h + k / 3 - 1) + dy;
        float sx = (float)(w + k % 3 - 1) + dx;
        float fy = floorf(sy), fx = floorf(sx);
        int iy = (int)fy, ix = (int)fx;
        float ly = sy - fy, lx = sx - fx;
        float wb[4];
        wb[0] = (1.f - ly) * (1.f - lx);
        wb[1] = (1.f - ly) * lx;
        wb[2] = ly * (1.f - lx);
        wb[3] = ly * lx;
        int base = tid * 4;
#pragma unroll
        for (int j = 0; j < 4; j++) {
            int yy = iy + (j >> 1);
            int xx = ix + (j & 1);
            bool ok = (yy >= 0) && (yy < H) && (xx >= 0) && (xx < W);
            int yc = min(max(yy, 0), H - 1);
            int xc = min(max(xx, 0), W - 1);
            cIdx[base + j] = yc * W + xc;
            cW[base + j] = ok ? wb[j] : 0.f;
        }
    }

    float acc[16];
#pragma unroll
    for (int i = 0; i < 16; i++) acc[i] = 0.f;

    const float* xb = x + (size_t)b * C_IN * HW;

    for (int c0 = 0; c0 < C_IN; c0 += 64) {
        __syncthreads();   // protects cIdx/cW (1st iter) and samp reuse (later)

        // ---- Phase 1: gather samp tile (64 ch x 9 taps) x 16 positions ----
        for (int e = tid; e < 576 * 16; e += 256) {
            int ck = e >> 4, p = e & 15;
            int cq = ck / 9;
            int k = ck - cq * 9;
            int c = c0 + cq;
            int cb = (k * 16 + p) * 4;
            const float* xc = xb + c * HW;
            float v = cW[cb + 0] * __ldg(xc + cIdx[cb + 0])
                    + cW[cb + 1] * __ldg(xc + cIdx[cb + 1])
                    + cW[cb + 2] * __ldg(xc + cIdx[cb + 2])
                    + cW[cb + 3] * __ldg(xc + cIdx[cb + 3]);
            samp[e] = v;
        }
        __syncthreads();

        // ---- Phase 2: accumulate; thread tid = output channel ----
        const float* wrow = wT + (size_t)(c0 * 9) * O_OUT + tid;
#pragma unroll 2
        for (int ckl = 0; ckl < 576; ckl++) {
            float wv = wrow[ckl * O_OUT];
            const float4* s4 = (const float4*)(samp + ckl * 16);
#pragma unroll
            for (int q = 0; q < 4; q++) {
                float4 s = s4[q];
                acc[4 * q + 0] += wv * s.x;
                acc[4 * q + 1] += wv * s.y;
                acc[4 * q + 2] += wv * s.z;
                acc[4 * q + 3] += wv * s.w;
            }
        }
    }

    // ---- Epilogue: stage through smem for coalesced stores ----
    __syncthreads();
    float* sAcc = samp;   // reuse (256*17 floats < 576*16)
#pragma unroll
    for (int p = 0; p < 16; p++) sAcc[tid * 17 + p] = acc[p];
    __syncthreads();

    float* ob = out + (size_t)b * O_OUT * HW + tileBase;
    for (int r = 0; r < 16; r++) {
        int o = r * 16 + (tid >> 4);
        int p = tid & 15;
        ob[(size_t)o * HW + p] = sAcc[o * 17 + p];
    }
}

// ---------------------------------------------------------------------------
// Launch
// ---------------------------------------------------------------------------
extern "C" void kernel_launch(void* const* d_in, const int* in_sizes, int n_in,
                              void* d_out, int out_size)
{
    const float* kernel_in = (const float*)d_in[0];  // 16x256x16x16
    const float* search_in = (const float*)d_in[1];  // 16x256x32x32
    const float* Toffset_w = (const float*)d_in[2];  // 18x256x3x3
    const float* Toffset_b = (const float*)d_in[3];  // 18
    const float* Tdeform_w = (const float*)d_in[4];  // 256x256x3x3
    const float* Soffset_w = (const float*)d_in[5];
    const float* Soffset_b = (const float*)d_in[6];
    const float* Sdeform_w = (const float*)d_in[7];

    float* out = (float*)d_out;
    float* kout = out;                       // 16*256*16*16 = 1,048,576
    float* sout = out + 1048576;             // 16*256*32*32 = 4,194,304
    float* koff = out + 5242880;             // 16*18*16*16  = 73,728
    float* soff = out + 5316608;             // 16*18*32*32  = 294,912

    // weight transposes (independent, tiny)
    transpose_w_kernel<<<CKTOT, 256>>>(Tdeform_w, 0);
    transpose_w_kernel<<<CKTOT, 256>>>(Sdeform_w, 1);

    // offset convs (write directly into the output offset regions)
    offset_conv_kernel<16, 16><<<16 * 1, 256>>>(kernel_in, Toffset_w, Toffset_b, koff);
    offset_conv_kernel<32, 32><<<16 * 4, 256>>>(search_in, Soffset_w, Soffset_b, soff);

    // deformable convs (read offsets back from d_out)
    deform_conv_kernel<16, 16><<<16 * 16, 256>>>(kernel_in, koff, 0, kout);
    deform_conv_kernel<32, 32><<<16 * 64, 256>>>(search_in, soff, 1, sout);
}

// round 4
// speedup vs baseline: 1.2373x; 1.2373x over previous
#include <cuda_runtime.h>

#define C_IN 256
#define O_OUT 256
#define CKTOT 2304   // C_IN * 9

// Transposed deform weights: wT[ck][o], ck = c*9+k. Static device scratch (no allocs).
__device__ float g_wT_T[CKTOT * O_OUT];
__device__ float g_wT_S[CKTOT * O_OUT];

// Split-C partial sums for the offset convs.
__device__ float g_part_S[4 * 16 * 18 * 1024];   // 4 groups, B=16, 18 oc, 32x32
__device__ float g_part_T[8 * 16 * 18 * 256];    // 8 groups, B=16, 18 oc, 16x16

// ---------------------------------------------------------------------------
// Weight transpose: w[o][c][3][3] -> wT[c*9+k][o]
// ---------------------------------------------------------------------------
__global__ void transpose_w_kernel(const float* __restrict__ w, int which) {
    float* wT = which ? g_wT_S : g_wT_T;
    int t = blockIdx.x * 256 + threadIdx.x;
    if (t < CKTOT * O_OUT) {
        int ck = t >> 8;
        int o  = t & 255;
        wT[t] = w[o * CKTOT + ck];
    }
}

// ---------------------------------------------------------------------------
// Offset conv partial: 3x3, stride 1, pad 1, computes a CG-channel slice of
// the 256->18 conv into the partial buffer (no bias).
// One block = one 16x16 spatial tile x one channel group. 256 threads.
// ---------------------------------------------------------------------------
template <int H, int W, int G>
__global__ void __launch_bounds__(256) offset_conv_part_kernel(
    const float* __restrict__ x, const float* __restrict__ wgt,
    float* __restrict__ part)
{
    const int HW = H * W;
    const int tiles = (H / 16) * (W / 16);
    const int CG = C_IN / G;

    const int b    = blockIdx.x / (tiles * G);
    int rem        = blockIdx.x % (tiles * G);
    const int tile = rem / G;
    const int g    = rem % G;
    const int h0 = (tile / (W / 16)) * 16;
    const int w0 = (tile % (W / 16)) * 16;
    const int c_start = g * CG;

    __shared__ float sx[8 * 18 * 18];   // 8 channels, 18x18 halo tile
    __shared__ float sw[18 * 8 * 9];    // 18 out-ch, 8 in-ch, 9 taps

    const int tid = threadIdx.x;
    const int ty = tid >> 4, tx = tid & 15;

    float acc[18];
#pragma unroll
    for (int i = 0; i < 18; i++) acc[i] = 0.f;

    const float* xb = x + (size_t)b * C_IN * HW;

    for (int c0 = c_start; c0 < c_start + CG; c0 += 8) {
        __syncthreads();
        for (int e = tid; e < 8 * 324; e += 256) {
            int c = e / 324, r = e % 324;
            int yy = r / 18 - 1 + h0;
            int xx = r % 18 - 1 + w0;
            float v = 0.f;
            if (yy >= 0 && yy < H && xx >= 0 && xx < W)
                v = xb[(c0 + c) * HW + yy * W + xx];
            sx[e] = v;
        }
        for (int e = tid; e < 18 * 72; e += 256) {
            int oc = e / 72, r = e % 72;
            sw[e] = wgt[oc * CKTOT + c0 * 9 + r];
        }
        __syncthreads();

#pragma unroll
        for (int c = 0; c < 8; c++) {
            float xv[9];
#pragma unroll
            for (int t = 0; t < 9; t++)
                xv[t] = sx[c * 324 + (ty + t / 3) * 18 + (tx + t % 3)];
#pragma unroll
            for (int oc = 0; oc < 18; oc++) {
#pragma unroll
                for (int t = 0; t < 9; t++)
                    acc[oc] += xv[t] * sw[oc * 72 + c * 9 + t];
            }
        }
    }

    const int h = h0 + ty, w = w0 + tx;
    float* ob = part + (size_t)g * 16 * 18 * HW + (size_t)b * 18 * HW + h * W + w;
#pragma unroll
    for (int oc = 0; oc < 18; oc++)
        ob[oc * HW] = acc[oc];
}

// ---------------------------------------------------------------------------
// Reduce partials + bias -> final offset tensor (d_out region).
// ---------------------------------------------------------------------------
template <int G>
__global__ void reduce_offset_kernel(const float* __restrict__ part,
                                     const float* __restrict__ bias,
                                     float* __restrict__ out,
                                     int perG, int HW)
{
    int i = blockIdx.x * 256 + threadIdx.x;
    if (i >= perG) return;
    float s = 0.f;
#pragma unroll
    for (int g = 0; g < G; g++) s += part[(size_t)g * perG + i];
    int oc = (i / HW) % 18;
    out[i] = s + bias[oc];
}

// ---------------------------------------------------------------------------
// Deformable conv v1 (3x3, pad 1, 1 group, no bias).
// One block = P contiguous (row-major) spatial positions of one batch.
// Phase 0: bilinear corner idx/weights per (tap, pos) -> smem.
// Phase 1: gather samp[ck_local][p] for a 64-channel chunk (576 x P tile).
// Phase 2: thread = output channel; f32x2 packed-FMA GEMM over 576 ck/chunk.
// Dynamic smem: samp[576*P] | cW[9*P*4] | cIdx[9*P*4]
// ---------------------------------------------------------------------------
template <int H, int W, int P>
__global__ void __launch_bounds__(256) deform_conv_kernel(
    const float* __restrict__ x, const float* __restrict__ off,
    int which, float* __restrict__ out)
{
    const int HW = H * W;
    const int nT = HW / P;
    const int b = blockIdx.x / nT;
    const int tileBase = (blockIdx.x % nT) * P;
    const float* wT = which ? g_wT_S : g_wT_T;

    extern __shared__ float smem[];
    float* samp = smem;                       // 576 * P
    float* cW   = smem + 576 * P;             // 9 * P * 4
    int*   cIdx = (int*)(cW + 9 * P * 4);     // 9 * P * 4

    const int tid = threadIdx.x;

    // ---- Phase 0: bilinear corners for 9 taps x P positions ----
    for (int e = tid; e < 9 * P; e += 256) {
        int k = e / P, p = e % P;
        int pos = tileBase + p;
        int h = pos / W, w = pos % W;
        const float* ob = off + (size_t)b * 18 * HW + pos;
        float dy = ob[(2 * k) * HW];
        float dx = ob[(2 * k + 1) * HW];
        float sy = (float)(h + k / 3 - 1) + dy;
        float sx = (float)(w + k % 3 - 1) + dx;
        float fy = floorf(sy), fx = floorf(sx);
        int iy = (int)fy, ix = (int)fx;
        float ly = sy - fy, lx = sx - fx;
        float wb[4];
        wb[0] = (1.f - ly) * (1.f - lx);
        wb[1] = (1.f - ly) * lx;
        wb[2] = ly * (1.f - lx);
        wb[3] = ly * lx;
        int base = e * 4;
#pragma unroll
        for (int j = 0; j < 4; j++) {
            int yy = iy + (j >> 1);
            int xx = ix + (j & 1);
            bool ok = (yy >= 0) && (yy < H) && (xx >= 0) && (xx < W);
            int yc = min(max(yy, 0), H - 1);
            int xc = min(max(xx, 0), W - 1);
            cIdx[base + j] = yc * W + xc;
            cW[base + j] = ok ? wb[j] : 0.f;
        }
    }

    unsigned long long acc2[P / 2];
#pragma unroll
    for (int i = 0; i < P / 2; i++) acc2[i] = 0ULL;

    const float* xb = x + (size_t)b * C_IN * HW;

    for (int c0 = 0; c0 < C_IN; c0 += 64) {
        __syncthreads();   // protects cIdx/cW (1st iter) and samp reuse (later)

        // ---- Phase 1: gather samp tile (64 ch x 9 taps) x P positions ----
        for (int e = tid; e < 576 * P; e += 256) {
            int ck = e / P, p = e % P;
            int cq = ck / 9;
            int k = ck - cq * 9;
            int c = c0 + cq;
            int cb = (k * P + p) * 4;
            const float* xc = xb + c * HW;
            float v = cW[cb + 0] * __ldg(xc + cIdx[cb + 0])
                    + cW[cb + 1] * __ldg(xc + cIdx[cb + 1])
                    + cW[cb + 2] * __ldg(xc + cIdx[cb + 2])
                    + cW[cb + 3] * __ldg(xc + cIdx[cb + 3]);
            samp[e] = v;
        }
        __syncthreads();

        // ---- Phase 2: f32x2 packed FMA; thread tid = output channel ----
        const float* wrow = wT + (size_t)(c0 * 9) * O_OUT + tid;
#pragma unroll 2
        for (int ckl = 0; ckl < 576; ckl++) {
            float wv = wrow[ckl * O_OUT];
            unsigned long long w2;
            asm("mov.b64 %0, {%1, %1};" : "=l"(w2) : "r"(__float_as_uint(wv)));
            const ulonglong2* s4 = (const ulonglong2*)(samp + ckl * P);
#pragma unroll
            for (int q = 0; q < P / 4; q++) {
                ulonglong2 s = s4[q];
                asm("fma.rn.f32x2 %0, %1, %2, %0;" : "+l"(acc2[2 * q + 0]) : "l"(w2), "l"(s.x));
                asm("fma.rn.f32x2 %0, %1, %2, %0;" : "+l"(acc2[2 * q + 1]) : "l"(w2), "l"(s.y));
            }
        }
    }

    // ---- Epilogue: stage through smem for coalesced stores ----
    __syncthreads();
    float* sAcc = samp;   // reuse: 256*(P+1) floats <= 576*P
#pragma unroll
    for (int i = 0; i < P / 2; i++) {
        unsigned lo, hi;
        asm("mov.b64 {%0, %1}, %2;" : "=r"(lo), "=r"(hi) : "l"(acc2[i]));
        sAcc[tid * (P + 1) + 2 * i + 0] = __uint_as_float(lo);
        sAcc[tid * (P + 1) + 2 * i + 1] = __uint_as_float(hi);
    }
    __syncthreads();

    float* ob = out + (size_t)b * O_OUT * HW + tileBase;
    const int rowsPerIter = 256 / P;
#pragma unroll 4
    for (int r = 0; r < P; r++) {
        int o = r * rowsPerIter + tid / P;
        int p = tid % P;
        ob[(size_t)o * HW + p] = sAcc[o * (P + 1) + p];
    }
}

// ---------------------------------------------------------------------------
// Launch
// ---------------------------------------------------------------------------
extern "C" void kernel_launch(void* const* d_in, const int* in_sizes, int n_in,
                              void* d_out, int out_size)
{
    const float* kernel_in = (const float*)d_in[0];  // 16x256x16x16
    const float* search_in = (const float*)d_in[1];  // 16x256x32x32
    const float* Toffset_w = (const float*)d_in[2];  // 18x256x3x3
    const float* Toffset_b = (const float*)d_in[3];  // 18
    const float* Tdeform_w = (const float*)d_in[4];  // 256x256x3x3
    const float* Soffset_w = (const float*)d_in[5];
    const float* Soffset_b = (const float*)d_in[6];
    const float* Sdeform_w = (const float*)d_in[7];

    float* out = (float*)d_out;
    float* kout = out;                       // 16*256*16*16 = 1,048,576
    float* sout = out + 1048576;             // 16*256*32*32 = 4,194,304
    float* koff = out + 5242880;             // 16*18*16*16  = 73,728
    float* soff = out + 5316608;             // 16*18*32*32  = 294,912

    // Dynamic smem sizes for deform kernels (opt-in > 48 KB for P=32).
    const int smemK = (576 * 16 + 2 * 9 * 16 * 4) * 4;   // 41,472 B
    const int smemS = (576 * 32 + 2 * 9 * 32 * 4) * 4;   // 82,944 B
    static int attr_done = 0;
    if (!attr_done) {
        cudaFuncSetAttribute((const void*)deform_conv_kernel<16, 16, 16>,
                             cudaFuncAttributeMaxDynamicSharedMemorySize, smemK);
        cudaFuncSetAttribute((const void*)deform_conv_kernel<32, 32, 32>,
                             cudaFuncAttributeMaxDynamicSharedMemorySize, smemS);
        attr_done = 1;
    }

    // weight transposes (independent, tiny)
    transpose_w_kernel<<<CKTOT, 256>>>(Tdeform_w, 0);
    transpose_w_kernel<<<CKTOT, 256>>>(Sdeform_w, 1);

    // offset convs: split-C partials -> reduce(+bias) into d_out offset regions
    float* partT; cudaGetSymbolAddress((void**)&partT, g_part_T);
    float* partS; cudaGetSymbolAddress((void**)&partS, g_part_S);

    offset_conv_part_kernel<16, 16, 8><<<16 * 1 * 8, 256>>>(kernel_in, Toffset_w, partT);
    offset_conv_part_kernel<32, 32, 4><<<16 * 4 * 4, 256>>>(search_in, Soffset_w, partS);

    reduce_offset_kernel<8><<<(16 * 18 * 256 + 255) / 256, 256>>>(
        partT, Toffset_b, koff, 16 * 18 * 256, 256);
    reduce_offset_kernel<4><<<(16 * 18 * 1024 + 255) / 256, 256>>>(
        partS, Soffset_b, soff, 16 * 18 * 1024, 1024);

    // deformable convs (read offsets back from d_out)
    deform_conv_kernel<16, 16, 16><<<16 * 16, 256, smemK>>>(kernel_in, koff, 0, kout);
    deform_conv_kernel<32, 32, 32><<<16 * 32, 256, smemS>>>(search_in, soff, 1, sout);
}

// round 7
// speedup vs baseline: 1.6998x; 1.3738x over previous
#include <cuda_runtime.h>

#define C_IN 256
#define O_OUT 256
#define CKTOT 2304   // C_IN * 9

// Transposed deform weights: wT[ck][o], ck = c*9+k. Static device scratch (no allocs).
__device__ float g_wT_T[CKTOT * O_OUT];
__device__ float g_wT_S[CKTOT * O_OUT];

// Split-C partial sums for the offset convs (G=8 both).
__device__ float g_part_S[8 * 16 * 18 * 1024];
__device__ float g_part_T[8 * 16 * 18 * 256];

// ---------------------------------------------------------------------------
// Weight transpose: w[o][c][3][3] -> wT[c*9+k][o]
// ---------------------------------------------------------------------------
__global__ void transpose_w_kernel(const float* __restrict__ w, int which) {
    float* wT = which ? g_wT_S : g_wT_T;
    int t = blockIdx.x * 256 + threadIdx.x;
    if (t < CKTOT * O_OUT) {
        int ck = t >> 8;
        int o  = t & 255;
        wT[t] = w[o * CKTOT + ck];
    }
}

// ---------------------------------------------------------------------------
// Offset conv partial: 3x3, stride 1, pad 1, CG-channel slice of 256->18.
// One block = one 16x16 spatial tile x one channel group. 256 threads.
// ---------------------------------------------------------------------------
template <int H, int W, int G>
__global__ void __launch_bounds__(256) offset_conv_part_kernel(
    const float* __restrict__ x, const float* __restrict__ wgt,
    float* __restrict__ part)
{
    const int HW = H * W;
    const int tiles = (H / 16) * (W / 16);
    const int CG = C_IN / G;

    const int b    = blockIdx.x / (tiles * G);
    int rem        = blockIdx.x % (tiles * G);
    const int tile = rem / G;
    const int g    = rem % G;
    const int h0 = (tile / (W / 16)) * 16;
    const int w0 = (tile % (W / 16)) * 16;
    const int c_start = g * CG;

    __shared__ float sx[8 * 18 * 18];
    __shared__ float sw[18 * 8 * 9];

    const int tid = threadIdx.x;
    const int ty = tid >> 4, tx = tid & 15;

    float acc[18];
#pragma unroll
    for (int i = 0; i < 18; i++) acc[i] = 0.f;

    const float* xb = x + (size_t)b * C_IN * HW;

    for (int c0 = c_start; c0 < c_start + CG; c0 += 8) {
        __syncthreads();
        for (int e = tid; e < 8 * 324; e += 256) {
            int c = e / 324, r = e % 324;
            int yy = r / 18 - 1 + h0;
            int xx = r % 18 - 1 + w0;
            float v = 0.f;
            if (yy >= 0 && yy < H && xx >= 0 && xx < W)
                v = xb[(c0 + c) * HW + yy * W + xx];
            sx[e] = v;
        }
        for (int e = tid; e < 18 * 72; e += 256) {
            int oc = e / 72, r = e % 72;
            sw[e] = wgt[oc * CKTOT + c0 * 9 + r];
        }
        __syncthreads();

#pragma unroll
        for (int c = 0; c < 8; c++) {
            float xv[9];
#pragma unroll
            for (int t = 0; t < 9; t++)
                xv[t] = sx[c * 324 + (ty + t / 3) * 18 + (tx + t % 3)];
#pragma unroll
            for (int oc = 0; oc < 18; oc++) {
#pragma unroll
                for (int t = 0; t < 9; t++)
                    acc[oc] += xv[t] * sw[oc * 72 + c * 9 + t];
            }
        }
    }

    const int h = h0 + ty, w = w0 + tx;
    float* ob = part + (size_t)g * 16 * 18 * HW + (size_t)b * 18 * HW + h * W + w;
#pragma unroll
    for (int oc = 0; oc < 18; oc++)
        ob[oc * HW] = acc[oc];
}

// ---------------------------------------------------------------------------
// Reduce partials + bias -> final offset tensor (d_out region).
// ---------------------------------------------------------------------------
template <int G>
__global__ void reduce_offset_kernel(const float* __restrict__ part,
                                     const float* __restrict__ bias,
                                     float* __restrict__ out,
                                     int perG, int HW)
{
    int i = blockIdx.x * 256 + threadIdx.x;
    if (i >= perG) return;
    float s = 0.f;
#pragma unroll
    for (int g = 0; g < G; g++) s += part[(size_t)g * perG + i];
    int oc = (i / HW) % 18;
    out[i] = s + bias[oc];
}

// ---------------------------------------------------------------------------
// Deformable conv v1 (3x3, pad 1, 1 group, no bias). P=32 pixels per block.
// Phase 0: bilinear corner idx/weights (float4/int4) -> smem.
// Phase 1: gather samp[576][32] for a 64-channel chunk.
// Phase 2: register-blocked GEMM: thread = 4 out-ch x 8 pixels, f32x2 FMAs.
// Dynamic smem: samp[576*32] | cWv[288 float4] | cIv[288 int4]  = 82,944 B
// ---------------------------------------------------------------------------
template <int H, int W>
__global__ void __launch_bounds__(256, 2) deform_conv_kernel(
    const float* __restrict__ x, const float* __restrict__ off,
    int which, float* __restrict__ out)
{
    const int HW = H * W;
    const int nT = HW / 32;
    const int b = blockIdx.x / nT;
    const int tileBase = (blockIdx.x % nT) * 32;
    const float* wT = which ? g_wT_S : g_wT_T;

    extern __shared__ float smem[];
    float*  samp = smem;                               // 576*32 floats
    float4* cWv  = (float4*)(smem + 576 * 32);         // 288 float4
    int4*   cIv  = (int4*)(cWv + 288);                 // 288 int4

    const int tid = threadIdx.x;

    // ---- Phase 0: bilinear corners for 9 taps x 32 positions ----
    for (int e = tid; e < 288; e += 256) {
        int k = e >> 5, p = e & 31;
        int pos = tileBase + p;
        int h = pos / W, w = pos % W;
        const float* ob = off + (size_t)b * 18 * HW + pos;
        float dy = ob[(2 * k) * HW];
        float dx = ob[(2 * k + 1) * HW];
        float sy = (float)(h + k / 3 - 1) + dy;
        float sx = (float)(w + k % 3 - 1) + dx;
        float fy = floorf(sy), fx = floorf(sx);
        int iy = (int)fy, ix = (int)fx;
        float ly = sy - fy, lx = sx - fx;
        float wb[4];
        wb[0] = (1.f - ly) * (1.f - lx);
        wb[1] = (1.f - ly) * lx;
        wb[2] = ly * (1.f - lx);
        wb[3] = ly * lx;
        int ic[4];
        float wc[4];
#pragma unroll
        for (int j = 0; j < 4; j++) {
            int yy = iy + (j >> 1);
            int xx = ix + (j & 1);
            bool ok = (yy >= 0) && (yy < H) && (xx >= 0) && (xx < W);
            int yc = min(max(yy, 0), H - 1);
            int xc = min(max(xx, 0), W - 1);
            ic[j] = yc * W + xc;
            wc[j] = ok ? wb[j] : 0.f;
        }
        cWv[e] = make_float4(wc[0], wc[1], wc[2], wc[3]);
        cIv[e] = make_int4(ic[0], ic[1], ic[2], ic[3]);
    }

    // Thread tile: 4 out-channels x 8 pixels.
    const int pG = tid >> 6;   // 0..3 -> pixels pG*8..+7
    const int oG = tid & 63;   // 0..63 -> out ch oG*4..+3

    unsigned long long acc2[16];   // [j][i2]: j = out-ch 0..3, i2 = pixel pair 0..3
#pragma unroll
    for (int i = 0; i < 16; i++) acc2[i] = 0ULL;

    const float* xb = x + (size_t)b * C_IN * HW;

    for (int c0 = 0; c0 < C_IN; c0 += 64) {
        __syncthreads();   // protects cWv/cIv (1st iter) and samp reuse (later)

        // ---- Phase 1: gather samp tile (64 ch x 9 taps) x 32 positions ----
        for (int e = tid; e < 576 * 32; e += 256) {
            int ck = e >> 5, p = e & 31;
            int cq = ck / 9;
            int k = ck - cq * 9;
            const float* xc = xb + (c0 + cq) * HW;
            float4 w4 = cWv[k * 32 + p];
            int4   i4 = cIv[k * 32 + p];
            samp[e] = w4.x * __ldg(xc + i4.x)
                    + w4.y * __ldg(xc + i4.y)
                    + w4.z * __ldg(xc + i4.z)
                    + w4.w * __ldg(xc + i4.w);
        }
        __syncthreads();

        // ---- Phase 2: register-blocked f32x2 GEMM ----
        // samp row = 32 floats = 8 ulonglong2; sp is offset by pG*8 floats.
        const float4* wp = (const float4*)(wT + (size_t)(c0 * 9) * O_OUT) + oG;
        const ulonglong2* sp = (const ulonglong2*)(samp + pG * 8);
#pragma unroll 4
        for (int ckl = 0; ckl < 576; ckl++) {
            float4 w4 = __ldg(wp + ckl * 64);          // 4 weights (LDG.128)
            ulonglong2 sA = sp[ckl * 8];               // pixels pG*8+0..3 (LDS.128)
            ulonglong2 sB = sp[ckl * 8 + 1];           // pixels pG*8+4..7 (LDS.128)
            unsigned long long w2[4];
            asm("mov.b64 %0, {%1, %1};" : "=l"(w2[0]) : "r"(__float_as_uint(w4.x)));
            asm("mov.b64 %0, {%1, %1};" : "=l"(w2[1]) : "r"(__float_as_uint(w4.y)));
            asm("mov.b64 %0, {%1, %1};" : "=l"(w2[2]) : "r"(__float_as_uint(w4.z)));
            asm("mov.b64 %0, {%1, %1};" : "=l"(w2[3]) : "r"(__float_as_uint(w4.w)));
#pragma unroll
            for (int j = 0; j < 4; j++) {
                asm("fma.rn.f32x2 %0, %1, %2, %0;" : "+l"(acc2[j * 4 + 0]) : "l"(w2[j]), "l"(sA.x));
                asm("fma.rn.f32x2 %0, %1, %2, %0;" : "+l"(acc2[j * 4 + 1]) : "l"(w2[j]), "l"(sA.y));
                asm("fma.rn.f32x2 %0, %1, %2, %0;" : "+l"(acc2[j * 4 + 2]) : "l"(w2[j]), "l"(sB.x));
                asm("fma.rn.f32x2 %0, %1, %2, %0;" : "+l"(acc2[j * 4 + 3]) : "l"(w2[j]), "l"(sB.y));
            }
        }
    }

    // ---- Epilogue: stage through smem (o x p, pad 33) for coalesced stores ----
    __syncthreads();
    float* sAcc = smem;   // 256*33 floats = 33.8 KB <= samp area
#pragma unroll
    for (int j = 0; j < 4; j++) {
        int o = oG * 4 + j;
#pragma unroll
        for (int i2 = 0; i2 < 4; i2++) {
            unsigned lo, hi;
            asm("mov.b64 {%0, %1}, %2;" : "=r"(lo), "=r"(hi) : "l"(acc2[j * 4 + i2]));
            sAcc[o * 33 + pG * 8 + 2 * i2 + 0] = __uint_as_float(lo);
            sAcc[o * 33 + pG * 8 + 2 * i2 + 1] = __uint_as_float(hi);
        }
    }
    __syncthreads();

    float* ob = out + (size_t)b * O_OUT * HW + tileBase;
    const int po = tid & 31;
    const int ro = tid >> 5;
#pragma unroll 8
    for (int r = 0; r < 32; r++) {
        int o = r * 8 + ro;
        ob[(size_t)o * HW + po] = sAcc[o * 33 + po];
    }
}

// ---------------------------------------------------------------------------
// Launch
// ---------------------------------------------------------------------------
extern "C" void kernel_launch(void* const* d_in, const int* in_sizes, int n_in,
                              void* d_out, int out_size)
{
    const float* kernel_in = (const float*)d_in[0];  // 16x256x16x16
    const float* search_in = (const float*)d_in[1];  // 16x256x32x32
    const float* Toffset_w = (const float*)d_in[2];  // 18x256x3x3
    const float* Toffset_b = (const float*)d_in[3];  // 18
    const float* Tdeform_w = (const float*)d_in[4];  // 256x256x3x3
    const float* Soffset_w = (const float*)d_in[5];
    const float* Soffset_b = (const float*)d_in[6];
    const float* Sdeform_w = (const float*)d_in[7];

    float* out = (float*)d_out;
    float* kout = out;                       // 16*256*16*16 = 1,048,576
    float* sout = out + 1048576;             // 16*256*32*32 = 4,194,304
    float* koff = out + 5242880;             // 16*18*16*16  = 73,728
    float* soff = out + 5316608;             // 16*18*32*32  = 294,912

    const int smemD = (576 * 32) * 4 + 288 * 16 + 288 * 16;   // 82,944 B
    static int attr_done = 0;
    if (!attr_done) {
        cudaFuncSetAttribute((const void*)deform_conv_kernel<16, 16>,
                             cudaFuncAttributeMaxDynamicSharedMemorySize, smemD);
        cudaFuncSetAttribute((const void*)deform_conv_kernel<32, 32>,
                             cudaFuncAttributeMaxDynamicSharedMemorySize, smemD);
        attr_done = 1;
    }

    // weight transposes (independent, tiny)
    transpose_w_kernel<<<CKTOT, 256>>>(Tdeform_w, 0);
    transpose_w_kernel<<<CKTOT, 256>>>(Sdeform_w, 1);

    // offset convs: split-C partials -> reduce(+bias) into d_out offset regions
    float* partT; cudaGetSymbolAddress((void**)&partT, g_part_T);
    float* partS; cudaGetSymbolAddress((void**)&partS, g_part_S);

    offset_conv_part_kernel<16, 16, 8><<<16 * 1 * 8, 256>>>(kernel_in, Toffset_w, partT);
    offset_conv_part_kernel<32, 32, 8><<<16 * 4 * 8, 256>>>(search_in, Soffset_w, partS);

    reduce_offset_kernel<8><<<(16 * 18 * 256 + 255) / 256, 256>>>(
        partT, Toffset_b, koff, 16 * 18 * 256, 256);
    reduce_offset_kernel<8><<<(16 * 18 * 1024 + 255) / 256, 256>>>(
        partS, Soffset_b, soff, 16 * 18 * 1024, 1024);

    // deformable convs (read offsets back from d_out)
    deform_conv_kernel<16, 16><<<16 * 8, 256, smemD>>>(kernel_in, koff, 0, kout);
    deform_conv_kernel<32, 32><<<16 * 32, 256, smemD>>>(search_in, soff, 1, sout);
}